// round 9
// baseline (speedup 1.0000x reference)
#include <cuda_runtime.h>
#include <math.h>
#include <stdint.h>

#define NRULES 1024
#define DMODEL 128
#define EDIM   256
#define TMAX   16
#define CAP    64      // P(Poisson(8) > 64) ~ 0
#define GRID   296     // persistent: 2/SM on 148-SM B300
#define NSLOT  5
#define CHUNKB 16384
#define CHUNKF 4096
#define XSTR   20
#define HSTR   20

// smem byte layout
#define WOFF   0
#define XOFF   (NSLOT * CHUNKB)                 // 81920
#define HOFF   (XOFF + DMODEL * XSTR * 4)       // 92160
#define TOKOFF (HOFF + EDIM * HSTR * 4)         // 112640
#define MBOFF  (TOKOFF + CAP * 4)               // 112896
#define SMEMSZ (MBOFF + NSLOT * 8 + 24)         // 112960 (x2 = 225920)

__device__ int g_is64 = 0;        // monotonic dtype flag
__device__ unsigned int g_next;   // work-steal counter (reset each replay)

__global__ void detect_kernel(const unsigned int* __restrict__ raw) {
    int i = threadIdx.x;
    if (i == 0) g_next = GRID;
    if (raw[2 * i + 1] != 0u) atomicOr(&g_is64, 1);
}

// ---------- PTX helpers ----------
__device__ __forceinline__ uint32_t smem_u32(const void* p) {
    uint32_t a;
    asm("{ .reg .u64 t; cvta.to.shared.u64 t, %1; cvt.u32.u64 %0, t; }" : "=r"(a) : "l"(p));
    return a;
}
__device__ __forceinline__ void mbar_init(uint32_t a, uint32_t cnt) {
    asm volatile("mbarrier.init.shared.b64 [%0], %1;" :: "r"(a), "r"(cnt) : "memory");
}
__device__ __forceinline__ void mbar_expect_tx(uint32_t a, uint32_t bytes) {
    asm volatile("mbarrier.arrive.expect_tx.shared.b64 _, [%0], %1;" :: "r"(a), "r"(bytes) : "memory");
}
__device__ __forceinline__ void bulk_g2s(uint32_t dst, const void* src, uint32_t bytes, uint32_t mbar) {
    asm volatile("cp.async.bulk.shared::cluster.global.mbarrier::complete_tx::bytes [%0], [%1], %2, [%3];"
                 :: "r"(dst), "l"(src), "r"(bytes), "r"(mbar) : "memory");
}
__device__ __forceinline__ void mbar_wait(uint32_t mbar, uint32_t parity) {
    asm volatile(
        "{\n\t.reg .pred P1;\n\t"
        "WAIT_%=:\n\t"
        "mbarrier.try_wait.parity.acquire.cta.shared::cta.b64 P1, [%0], %1, 0x989680;\n\t"
        "@P1 bra DONE_%=;\n\t"
        "bra WAIT_%=;\n\t"
        "DONE_%=:\n\t}"
        :: "r"(mbar), "r"(parity) : "memory");
}
__device__ __forceinline__ float gelu_exact(float v) {
    return 0.5f * v * (1.0f + erff(v * 0.70710678118654752f));
}
__device__ __forceinline__ const float* chunk_src(const float* W1r, const float* W2r, int idx) {
    return (idx < 8) ? (W1r + idx * CHUNKF) : (W2r + (idx - 8) * CHUNKF);
}
__device__ __forceinline__ void issue_chunk(uint32_t sb, uint32_t mb, unsigned K, const float* src) {
    const unsigned slot = K % NSLOT;
    mbar_expect_tx(mb + slot * 8, CHUNKB);
    bulk_g2s(sb + WOFF + slot * CHUNKB, src, CHUNKB, mb + slot * 8);
}

// Persistent CTAs, 256 threads, 2/SM. tid0 produces (TMA ring depth 5, 16KB chunks);
// all 256 threads consume from smem, each weight float read exactly once.
__global__ __launch_bounds__(256, 2) void ffn_kernel(
    const float* __restrict__ x,
    const void*  __restrict__ rules,
    const float* __restrict__ w1,
    const float* __restrict__ b1,
    const float* __restrict__ w2,
    const float* __restrict__ b2,
    float* __restrict__ out,
    int n)
{
    extern __shared__ __align__(128) char smem[];
    float* wbuf = (float*)(smem + WOFF);
    float* xs   = (float*)(smem + XOFF);
    float* hs   = (float*)(smem + HOFF);
    int*   toks = (int*)(smem + TOKOFF);
    const uint32_t sb = smem_u32(smem);
    const uint32_t mb = sb + MBOFF;

    __shared__ int s_cnt;
    __shared__ int s_rnext;

    const int tid = threadIdx.x;
    if (tid < NSLOT) mbar_init(mb + tid * 8, 1);
    __syncthreads();

    int r = blockIdx.x;
    unsigned kg = 0;   // absolute chunk counter (per CTA); parity = (K/NSLOT)&1

    if (tid == 0) {    // prime the ring for the first rule
        const float* W1r = w1 + (size_t)r * 32768;
        const float* W2r = w2 + (size_t)r * 32768;
        for (int i = 0; i < NSLOT; i++) issue_chunk(sb, mb, kg + i, chunk_src(W1r, W2r, i));
    }

    const int half = tid >> 7;       // layer2 e-half
    const int dcol = tid & 127;      // layer2 d-column

    while (r < NRULES) {
        if (tid == 0) s_cnt = 0;
        __syncthreads();

        // ---- gather this rule's tokens (vectorized scan; order irrelevant) ----
        if (g_is64 == 0) {
            const longlong2* rl = (const longlong2*)rules;
            for (int i = tid; i < n / 2; i += 256) {
                longlong2 v = rl[i];
                if ((int)v.x == r) { int p = atomicAdd(&s_cnt, 1); if (p < CAP) toks[p] = 2 * i; }
                if ((int)v.y == r) { int p = atomicAdd(&s_cnt, 1); if (p < CAP) toks[p] = 2 * i + 1; }
            }
        } else {
            const int4* rl = (const int4*)rules;
            for (int i = tid; i < n / 4; i += 256) {
                int4 v = rl[i];
                if (v.x == r) { int p = atomicAdd(&s_cnt, 1); if (p < CAP) toks[p] = 4 * i; }
                if (v.y == r) { int p = atomicAdd(&s_cnt, 1); if (p < CAP) toks[p] = 4 * i + 1; }
                if (v.z == r) { int p = atomicAdd(&s_cnt, 1); if (p < CAP) toks[p] = 4 * i + 2; }
                if (v.w == r) { int p = atomicAdd(&s_cnt, 1); if (p < CAP) toks[p] = 4 * i + 3; }
            }
        }
        __syncthreads();

        const int count = min(s_cnt, CAP);
        const int npass = (count > 0) ? (count + TMAX - 1) / TMAX : 1;  // stream ring even if empty
        const unsigned totalK = npass * 16;

        const float* W1r = w1 + (size_t)r * 32768;
        const float* W2r = w2 + (size_t)r * 32768;
        const float b1v = b1[(size_t)r * EDIM + tid];
        const float b2v = b2[(size_t)r * DMODEL + dcol];

        for (int pass = 0; pass < npass; pass++) {
            const int base = pass * TMAX;
            int T = count - base; if (T > TMAX) T = TMAX; if (T < 0) T = 0;
            const int NQ = (T + 3) >> 2;
            const int NT = NQ * 4;

            // ---- x tile, transposed xs[d][t] ----
            for (int i = tid; i < NT * DMODEL; i += 256) {
                int t = i >> 7, d = i & (DMODEL - 1);
                xs[d * XSTR + t] = (t < T) ? x[(size_t)toks[base + t] * DMODEL + d] : 0.0f;
            }
            __syncthreads();

            // ---- layer 1: chunks 0..7; thread owns e-column tid, NT accumulators ----
            float acc[TMAX];
#pragma unroll
            for (int t = 0; t < TMAX; t++) acc[t] = b1v;

            for (int c = 0; c < 8; c++) {
                const unsigned K = kg + pass * 16 + c;
                if (pass == 0 && c == 0 && tid == 0) s_rnext = (int)atomicAdd(&g_next, 1u);
                mbar_wait(mb + (K % NSLOT) * 8, (K / NSLOT) & 1);
                const float* Wc = wbuf + (K % NSLOT) * CHUNKF;   // [16][256]
#pragma unroll 4
                for (int dd = 0; dd < 16; dd++) {
                    const float w = Wc[dd * EDIM + tid];              // LDS.32 coalesced, read once
                    const float4* xq = (const float4*)&xs[(c * 16 + dd) * XSTR];
#pragma unroll
                    for (int q = 0; q < 4; q++) {
                        if (q < NQ) {
                            const float4 xv = xq[q];                  // broadcast LDS.128
                            acc[q * 4 + 0] += xv.x * w;
                            acc[q * 4 + 1] += xv.y * w;
                            acc[q * 4 + 2] += xv.z * w;
                            acc[q * 4 + 3] += xv.w * w;
                        }
                    }
                }
                if (c == 7) {   // gelu + hs store before the barrier
                    for (int q = 0; q < NQ; q++) {
                        float4 hv;
                        hv.x = gelu_exact(acc[q * 4 + 0]);
                        hv.y = gelu_exact(acc[q * 4 + 1]);
                        hv.z = gelu_exact(acc[q * 4 + 2]);
                        hv.w = gelu_exact(acc[q * 4 + 3]);
                        *(float4*)&hs[tid * HSTR + q * 4] = hv;
                    }
                }
                __syncthreads();   // slot reads done (+ hs visible at c==7)
                if (tid == 0) {    // refill this rule, or prefetch next rule
                    const unsigned nxt = K + NSLOT;
                    if (nxt < kg + totalK) {
                        issue_chunk(sb, mb, nxt, chunk_src(W1r, W2r, (int)((nxt - kg) & 15)));
                    } else {
                        const int rn = s_rnext;
                        if (rn < NRULES)
                            issue_chunk(sb, mb, nxt,
                                chunk_src(w1 + (size_t)rn * 32768, w2 + (size_t)rn * 32768,
                                          (int)(nxt - (kg + totalK))));
                    }
                }
            }

            // ---- layer 2: chunks 8..15; thread owns d-column dcol, e-half 'half' ----
            float acc2[TMAX];
#pragma unroll
            for (int t = 0; t < TMAX; t++) acc2[t] = 0.0f;

            for (int c = 8; c < 16; c++) {
                const unsigned K = kg + pass * 16 + c;
                mbar_wait(mb + (K % NSLOT) * 8, (K / NSLOT) & 1);
                if (((c - 8) >> 2) == half) {                 // this half's 4 chunks
                    const float* Wc = wbuf + (K % NSLOT) * CHUNKF;   // [32][128]
                    const int erow = ((c - 8) & 3) * 32 + (half << 7);
#pragma unroll 4
                    for (int ee = 0; ee < 32; ee++) {
                        const float w = Wc[ee * DMODEL + dcol];       // LDS.32 coalesced, read once
                        const float4* hq = (const float4*)&hs[(erow + ee) * HSTR];
#pragma unroll
                        for (int q = 0; q < 4; q++) {
                            if (q < NQ) {
                                const float4 hv = hq[q];              // broadcast LDS.128
                                acc2[q * 4 + 0] += hv.x * w;
                                acc2[q * 4 + 1] += hv.y * w;
                                acc2[q * 4 + 2] += hv.z * w;
                                acc2[q * 4 + 3] += hv.w * w;
                            }
                        }
                    }
                }
                __syncthreads();
                if (tid == 0) {
                    const unsigned nxt = K + NSLOT;
                    if (nxt < kg + totalK) {
                        issue_chunk(sb, mb, nxt, chunk_src(W1r, W2r, (int)((nxt - kg) & 15)));
                    } else {
                        const int rn = s_rnext;
                        if (rn < NRULES)
                            issue_chunk(sb, mb, nxt,
                                chunk_src(w1 + (size_t)rn * 32768, w2 + (size_t)rn * 32768,
                                          (int)(nxt - (kg + totalK))));
                    }
                }
            }

            // ---- reduce e-halves via xs, add bias, store ----
            if (half == 1) {
                for (int q = 0; q < NQ; q++) {
                    float4 pv;
                    pv.x = acc2[q * 4 + 0]; pv.y = acc2[q * 4 + 1];
                    pv.z = acc2[q * 4 + 2]; pv.w = acc2[q * 4 + 3];
                    *(float4*)&xs[dcol * XSTR + q * 4] = pv;
                }
            }
            __syncthreads();
            if (half == 0) {
                for (int q = 0; q < NQ; q++) {
                    const float4 pv = *(const float4*)&xs[dcol * XSTR + q * 4];
                    acc2[q * 4 + 0] += pv.x;
                    acc2[q * 4 + 1] += pv.y;
                    acc2[q * 4 + 2] += pv.z;
                    acc2[q * 4 + 3] += pv.w;
                }
                for (int t = 0; t < T; t++)
                    out[(size_t)toks[base + t] * DMODEL + dcol] = acc2[t] + b2v;  // coalesced
            }
            __syncthreads();   // xs/toks reuse safety
        }

        kg += totalK;
        r = s_rnext;
    }
}

extern "C" void kernel_launch(void* const* d_in, const int* in_sizes, int n_in,
                              void* d_out, int out_size)
{
    const float* x     = (const float*)d_in[0];
    const void*  rules = d_in[1];
    const float* w1    = (const float*)d_in[2];
    const float* b1    = (const float*)d_in[3];
    const float* w2    = (const float*)d_in[4];
    const float* b2    = (const float*)d_in[5];
    float*       out   = (float*)d_out;

    const int n = in_sizes[1];

    cudaFuncSetAttribute(ffn_kernel, cudaFuncAttributeMaxDynamicSharedMemorySize, SMEMSZ);

    detect_kernel<<<1, 256>>>((const unsigned int*)rules);   // also resets g_next
    ffn_kernel<<<GRID, 256, SMEMSZ>>>(x, rules, w1, b1, w2, b2, out, n);
}

// round 11
// speedup vs baseline: 1.2241x; 1.2241x over previous
#include <cuda_runtime.h>
#include <math.h>
#include <stdint.h>

#define NRULES 1024
#define DMODEL 128
#define EDIM   256
#define TMAX   16
#define CAP    64      // P(Poisson(8) > 64) ~ 0
#define GRID   296     // persistent: 2/SM on 148-SM B300
#define NSLOT  5
#define CHUNKB 16384
#define CHUNKF 4096
#define XSTR   20
#define HSTR   20

// smem byte layout
#define WOFF   0
#define XOFF   (NSLOT * CHUNKB)                 // 81920
#define HOFF   (XOFF + DMODEL * XSTR * 4)       // 92160
#define TOKOFF (HOFF + EDIM * HSTR * 4)         // 112640
#define MBOFF  (TOKOFF + CAP * 4)               // 112896
#define SMEMSZ (MBOFF + NSLOT * 8 + 24)         // 112960 (x2 = 225920 <= 227KB)

__device__ int g_is64 = 0;        // monotonic dtype flag
__device__ unsigned int g_next;   // work-steal counter (reset each replay)

__global__ void detect_kernel(const unsigned int* __restrict__ raw) {
    int i = threadIdx.x;
    if (i == 0) g_next = GRID;
    if (raw[2 * i + 1] != 0u) atomicOr(&g_is64, 1);
}

// ---------- PTX helpers ----------
__device__ __forceinline__ uint32_t smem_u32(const void* p) {
    uint32_t a;
    asm("{ .reg .u64 t; cvta.to.shared.u64 t, %1; cvt.u32.u64 %0, t; }" : "=r"(a) : "l"(p));
    return a;
}
__device__ __forceinline__ void mbar_init(uint32_t a, uint32_t cnt) {
    asm volatile("mbarrier.init.shared.b64 [%0], %1;" :: "r"(a), "r"(cnt) : "memory");
}
__device__ __forceinline__ void mbar_expect_tx(uint32_t a, uint32_t bytes) {
    asm volatile("mbarrier.arrive.expect_tx.shared.b64 _, [%0], %1;" :: "r"(a), "r"(bytes) : "memory");
}
__device__ __forceinline__ void bulk_g2s(uint32_t dst, const void* src, uint32_t bytes, uint32_t mbar) {
    asm volatile("cp.async.bulk.shared::cluster.global.mbarrier::complete_tx::bytes [%0], [%1], %2, [%3];"
                 :: "r"(dst), "l"(src), "r"(bytes), "r"(mbar) : "memory");
}
__device__ __forceinline__ void mbar_wait(uint32_t mbar, uint32_t parity) {
    asm volatile(
        "{\n\t.reg .pred P1;\n\t"
        "WAIT_%=:\n\t"
        "mbarrier.try_wait.parity.acquire.cta.shared::cta.b64 P1, [%0], %1, 0x989680;\n\t"
        "@P1 bra DONE_%=;\n\t"
        "bra WAIT_%=;\n\t"
        "DONE_%=:\n\t}"
        :: "r"(mbar), "r"(parity) : "memory");
}
__device__ __forceinline__ float gelu_exact(float v) {
    return 0.5f * v * (1.0f + erff(v * 0.70710678118654752f));
}
__device__ __forceinline__ const float* chunk_src(const float* W1r, const float* W2r, int idx) {
    return (idx < 8) ? (W1r + idx * CHUNKF) : (W2r + (idx - 8) * CHUNKF);
}
__device__ __forceinline__ void issue_chunk(uint32_t sb, uint32_t mb, unsigned K, const float* src) {
    const unsigned slot = K % NSLOT;
    mbar_expect_tx(mb + slot * 8, CHUNKB);
    bulk_g2s(sb + WOFF + slot * CHUNKB, src, CHUNKB, mb + slot * 8);
}
__device__ __forceinline__ void refill(uint32_t sb, uint32_t mb, unsigned K,
    unsigned kstart, unsigned kend,
    const float* W1r, const float* W2r,
    const float* w1, const float* w2, int rnext)
{
    const unsigned nxt = K + NSLOT;
    if (nxt < kend) {
        issue_chunk(sb, mb, nxt, chunk_src(W1r, W2r, (int)((nxt - kstart) & 15)));
    } else if (rnext < NRULES) {
        issue_chunk(sb, mb, nxt,
            chunk_src(w1 + (size_t)rnext * 32768, w2 + (size_t)rnext * 32768,
                      (int)(nxt - kend)));
    }
}

// Persistent CTAs, 256 threads, 2/SM. tid0 produces (TMA ring depth 5, 16KB chunks);
// consumer math identical to the proven R7 kernel (4x4 register blocking).
__global__ __launch_bounds__(256, 2) void ffn_kernel(
    const float* __restrict__ x,
    const void*  __restrict__ rules,
    const float* __restrict__ w1,
    const float* __restrict__ b1,
    const float* __restrict__ w2,
    const float* __restrict__ b2,
    float* __restrict__ out,
    int n)
{
    extern __shared__ __align__(128) char smem[];
    float* wbuf = (float*)(smem + WOFF);
    float* xs   = (float*)(smem + XOFF);
    float* hs   = (float*)(smem + HOFF);
    int*   toks = (int*)(smem + TOKOFF);
    const uint32_t sb = smem_u32(smem);
    const uint32_t mb = sb + MBOFF;

    __shared__ int s_cnt;
    __shared__ int s_rnext;

    const int tid = threadIdx.x;
    if (tid < NSLOT) mbar_init(mb + tid * 8, 1);
    __syncthreads();

    int r = blockIdx.x;
    unsigned kg = 0;   // absolute chunk counter; slot = K % NSLOT, parity = (K/NSLOT)&1

    if (tid == 0) {    // prime the ring for the first rule
        const float* W1r = w1 + (size_t)r * 32768;
        const float* W2r = w2 + (size_t)r * 32768;
        for (int i = 0; i < NSLOT; i++) issue_chunk(sb, mb, kg + i, chunk_src(W1r, W2r, i));
    }

    // thread roles (R7 mapping)
    const int e0 = (tid & 63) * 4, tq1 = tid >> 6, t1 = tq1 * 4;                      // layer1
    const int dq = tid & 31, d0 = dq * 4, tq2 = (tid >> 5) & 3, eh = tid >> 7;        // layer2
    const int t2 = tq2 * 4;

    while (r < NRULES) {
        if (tid == 0) s_cnt = 0;
        __syncthreads();

        // ---- gather this rule's tokens (vectorized; order irrelevant) ----
        if (g_is64 == 0) {
            const longlong2* rl = (const longlong2*)rules;
            for (int i = tid; i < n / 2; i += 256) {
                longlong2 v = rl[i];
                if ((int)v.x == r) { int p = atomicAdd(&s_cnt, 1); if (p < CAP) toks[p] = 2 * i; }
                if ((int)v.y == r) { int p = atomicAdd(&s_cnt, 1); if (p < CAP) toks[p] = 2 * i + 1; }
            }
        } else {
            const int4* rl = (const int4*)rules;
            for (int i = tid; i < n / 4; i += 256) {
                int4 v = rl[i];
                if (v.x == r) { int p = atomicAdd(&s_cnt, 1); if (p < CAP) toks[p] = 4 * i; }
                if (v.y == r) { int p = atomicAdd(&s_cnt, 1); if (p < CAP) toks[p] = 4 * i + 1; }
                if (v.z == r) { int p = atomicAdd(&s_cnt, 1); if (p < CAP) toks[p] = 4 * i + 2; }
                if (v.w == r) { int p = atomicAdd(&s_cnt, 1); if (p < CAP) toks[p] = 4 * i + 3; }
            }
        }
        if (tid == 0) s_rnext = (int)atomicAdd(&g_next, 1u);   // steal next rule
        __syncthreads();

        const int count = min(s_cnt, CAP);
        const int npass = (count > 0) ? (count + TMAX - 1) / TMAX : 1;   // stream even if empty
        const unsigned totalK = npass * 16;
        const int rnext = s_rnext;

        const float* W1r = w1 + (size_t)r * 32768;
        const float* W2r = w2 + (size_t)r * 32768;

        for (int pass = 0; pass < npass; pass++) {
            const int base = pass * TMAX;
            int T = count - base; if (T > TMAX) T = TMAX; if (T < 0) T = 0;
            const int NQ = (T + 3) >> 2;     // 0 allowed (empty rule): gates disable compute
            const unsigned kpass = kg + pass * 16;
            const unsigned kend  = kg + totalK;

            // ---- x tile, transposed xs[d][t] ----
            for (int i = tid; i < NQ * 4 * DMODEL; i += 256) {
                int t = i >> 7, d = i & (DMODEL - 1);
                xs[d * XSTR + t] = (t < T) ? x[(size_t)toks[base + t] * DMODEL + d] : 0.0f;
            }
            __syncthreads();

            // ---- layer 1: chunks 0..7 (each 16 d-rows x 256 e) ----
            float acc[16];
            if (tq1 < NQ) {
                const float4 bv = *(const float4*)&b1[(size_t)r * EDIM + e0];
#pragma unroll
                for (int k = 0; k < 4; k++) {
                    acc[0 + k] = bv.x; acc[4 + k] = bv.y; acc[8 + k] = bv.z; acc[12 + k] = bv.w;
                }
            }
            for (int c = 0; c < 8; c++) {
                const unsigned K = kpass + c;
                mbar_wait(mb + (K % NSLOT) * 8, (K / NSLOT) & 1);
                if (tq1 < NQ) {
                    const float* Wc = wbuf + (K % NSLOT) * CHUNKF;     // [16][256]
#pragma unroll
                    for (int dd = 0; dd < 16; dd++) {
                        const float4 w4 = *(const float4*)&Wc[dd * EDIM + e0];
                        const float4 x4 = *(const float4*)&xs[(c * 16 + dd) * XSTR + t1];
                        const float wj[4] = {w4.x, w4.y, w4.z, w4.w};
                        const float xk[4] = {x4.x, x4.y, x4.z, x4.w};
#pragma unroll
                        for (int j = 0; j < 4; j++)
#pragma unroll
                            for (int k = 0; k < 4; k++)
                                acc[j * 4 + k] += wj[j] * xk[k];
                    }
                }
                if (c == 7 && tq1 < NQ) {     // gelu + hs store before the barrier
#pragma unroll
                    for (int j = 0; j < 4; j++) {
                        float4 hv;
                        hv.x = gelu_exact(acc[j * 4 + 0]);
                        hv.y = gelu_exact(acc[j * 4 + 1]);
                        hv.z = gelu_exact(acc[j * 4 + 2]);
                        hv.w = gelu_exact(acc[j * 4 + 3]);
                        *(float4*)&hs[(e0 + j) * HSTR + t1] = hv;
                    }
                }
                __syncthreads();               // slot reads done (+ hs visible at c==7)
                if (tid == 0) refill(sb, mb, K, kg, kend, W1r, W2r, w1, w2, rnext);
            }

            // ---- layer 2: chunks 8..15 (each 32 e-rows x 128 d), e split in halves ----
            float acc2[16];
#pragma unroll
            for (int i = 0; i < 16; i++) acc2[i] = 0.0f;

            for (int c = 8; c < 16; c++) {
                const unsigned K = kpass + c;
                mbar_wait(mb + (K % NSLOT) * 8, (K / NSLOT) & 1);
                if (tq2 < NQ && ((c - 8) >> 2) == eh) {
                    const float* Wc = wbuf + (K % NSLOT) * CHUNKF;     // [32][128]
                    const int erow = (c - 8) * 32;                      // global e row base
#pragma unroll
                    for (int ee = 0; ee < 32; ee++) {
                        const float4 w4 = *(const float4*)&Wc[ee * DMODEL + d0];
                        const float4 h4 = *(const float4*)&hs[(erow + ee) * HSTR + t2];
                        const float wj[4] = {w4.x, w4.y, w4.z, w4.w};
                        const float hk[4] = {h4.x, h4.y, h4.z, h4.w};
#pragma unroll
                        for (int j = 0; j < 4; j++)
#pragma unroll
                            for (int k = 0; k < 4; k++)
                                acc2[j * 4 + k] += wj[j] * hk[k];
                    }
                }
                __syncthreads();
                if (tid == 0) refill(sb, mb, K, kg, kend, W1r, W2r, w1, w2, rnext);
            }

            // ---- reduce e-halves via xs, add bias, store ----
            if (eh == 1 && tq2 < NQ) {
#pragma unroll
                for (int j = 0; j < 4; j++) {
                    float4 pv;
                    pv.x = acc2[j * 4 + 0]; pv.y = acc2[j * 4 + 1];
                    pv.z = acc2[j * 4 + 2]; pv.w = acc2[j * 4 + 3];
                    *(float4*)&xs[(d0 + j) * XSTR + t2] = pv;
                }
            }
            __syncthreads();
            if (eh == 0 && tq2 < NQ) {
                const float4 b2v = *(const float4*)&b2[(size_t)r * DMODEL + d0];
#pragma unroll
                for (int j = 0; j < 4; j++) {
                    const float4 pv = *(const float4*)&xs[(d0 + j) * XSTR + t2];
                    acc2[j * 4 + 0] += pv.x; acc2[j * 4 + 1] += pv.y;
                    acc2[j * 4 + 2] += pv.z; acc2[j * 4 + 3] += pv.w;
                }
#pragma unroll
                for (int k = 0; k < 4; k++) {
                    const int t = t2 + k;
                    if (t < T) {
                        float4 o;
                        o.x = acc2[0 + k]  + b2v.x;
                        o.y = acc2[4 + k]  + b2v.y;
                        o.z = acc2[8 + k]  + b2v.z;
                        o.w = acc2[12 + k] + b2v.w;
                        *(float4*)&out[(size_t)toks[base + t] * DMODEL + d0] = o;
                    }
                }
            }
            __syncthreads();   // xs/toks reuse safety
        }

        kg += totalK;
        r = rnext;
    }
}

extern "C" void kernel_launch(void* const* d_in, const int* in_sizes, int n_in,
                              void* d_out, int out_size)
{
    const float* x     = (const float*)d_in[0];
    const void*  rules = d_in[1];
    const float* w1    = (const float*)d_in[2];
    const float* b1    = (const float*)d_in[3];
    const float* w2    = (const float*)d_in[4];
    const float* b2    = (const float*)d_in[5];
    float*       out   = (float*)d_out;

    const int n = in_sizes[1];

    cudaFuncSetAttribute(ffn_kernel, cudaFuncAttributeMaxDynamicSharedMemorySize, SMEMSZ);

    detect_kernel<<<1, 256>>>((const unsigned int*)rules);   // also resets g_next
    ffn_kernel<<<GRID, 256, SMEMSZ>>>(x, rules, w1, b1, w2, b2, out, n);
}

// round 12
// speedup vs baseline: 1.2513x; 1.0222x over previous
#include <cuda_runtime.h>
#include <math.h>
#include <stdint.h>

#define NRULES 1024
#define DMODEL 128
#define EDIM   256
#define TMAX   16
#define CAP    64      // P(Poisson(8) > 64) ~ 0
#define GRID   296     // persistent: 2/SM
#define NSLOT  4
#define CHUNKB 16384
#define CHUNKF 4096
#define XSTR   20      // x tile stride (floats)
#define HSTR   20      // hs tile stride

// smem byte layout
#define WOFF   0
#define HOFF   (NSLOT * CHUNKB)                 // 65536
#define SOFF   (HOFF + EDIM * HSTR * 4)         // 86016 : scratch 3584 floats (14336B)
#define TOKOFF (SOFF + 14336)                   // 100352
#define MBOFF  (TOKOFF + CAP * 4)               // 100608
#define SMEMSZ (MBOFF + NSLOT * 8 + 32)         // 100672 (x2 = 201344 <= 227KB)

__device__ int g_is64 = 0;        // monotonic dtype flag
__device__ unsigned int g_next;   // work-steal counter (reset each replay)

__global__ void detect_kernel(const unsigned int* __restrict__ raw) {
    int i = threadIdx.x;
    if (i == 0) g_next = GRID;
    if (raw[2 * i + 1] != 0u) atomicOr(&g_is64, 1);
}

// ---------- PTX helpers ----------
__device__ __forceinline__ uint32_t smem_u32(const void* p) {
    uint32_t a;
    asm("{ .reg .u64 t; cvta.to.shared.u64 t, %1; cvt.u32.u64 %0, t; }" : "=r"(a) : "l"(p));
    return a;
}
__device__ __forceinline__ void mbar_init(uint32_t a, uint32_t cnt) {
    asm volatile("mbarrier.init.shared.b64 [%0], %1;" :: "r"(a), "r"(cnt) : "memory");
}
__device__ __forceinline__ void mbar_expect_tx(uint32_t a, uint32_t bytes) {
    asm volatile("mbarrier.arrive.expect_tx.shared.b64 _, [%0], %1;" :: "r"(a), "r"(bytes) : "memory");
}
__device__ __forceinline__ void bulk_g2s(uint32_t dst, const void* src, uint32_t bytes, uint32_t mbar) {
    asm volatile("cp.async.bulk.shared::cluster.global.mbarrier::complete_tx::bytes [%0], [%1], %2, [%3];"
                 :: "r"(dst), "l"(src), "r"(bytes), "r"(mbar) : "memory");
}
__device__ __forceinline__ void mbar_wait(uint32_t mbar, uint32_t parity) {
    asm volatile(
        "{\n\t.reg .pred P1;\n\t"
        "WAIT_%=:\n\t"
        "mbarrier.try_wait.parity.acquire.cta.shared::cta.b64 P1, [%0], %1, 0x989680;\n\t"
        "@P1 bra DONE_%=;\n\t"
        "bra WAIT_%=;\n\t"
        "DONE_%=:\n\t}"
        :: "r"(mbar), "r"(parity) : "memory");
}
__device__ __forceinline__ float gelu_exact(float v) {
    return 0.5f * v * (1.0f + erff(v * 0.70710678118654752f));
}
__device__ __forceinline__ const float* chunk_src(const float* W1r, const float* W2r, int idx) {
    return (idx < 8) ? (W1r + idx * CHUNKF) : (W2r + (idx - 8) * CHUNKF);
}
__device__ __forceinline__ void issue_chunk(uint32_t sb, uint32_t mb, unsigned K, const float* src) {
    const unsigned slot = K & 3;
    mbar_expect_tx(mb + slot * 8, CHUNKB);
    bulk_g2s(sb + WOFF + slot * CHUNKB, src, CHUNKB, mb + slot * 8);
}
__device__ __forceinline__ void refill(uint32_t sb, uint32_t mb, unsigned K,
    unsigned kstart, unsigned kend,
    const float* W1r, const float* W2r,
    const float* w1, const float* w2, int rnext)
{
    const unsigned nxt = K + NSLOT;
    if (nxt < kend) {
        issue_chunk(sb, mb, nxt, chunk_src(W1r, W2r, (int)((nxt - kstart) & 15)));
    } else if (rnext < NRULES) {
        issue_chunk(sb, mb, nxt,
            chunk_src(w1 + (size_t)rnext * 32768, w2 + (size_t)rnext * 32768,
                      (int)(nxt - kend)));
    }
}

// One pass over <=16 tokens, NQ in {1,2,4} token-quads (compile time).
// EVERY chunk is consumed by all 8 warps; partials reduced via scratch
// with collision-free stride TW = NQ*4.
template<int NQ>
__device__ __forceinline__ void run_pass(
    const float* __restrict__ x,
    const float* W1r, const float* W2r,
    const float* b1r, const float* b2r,
    float* __restrict__ out,
    float* wbuf, float* hs, float* scratch, const int* toks,
    uint32_t sb, uint32_t mb,
    int T, int tid, unsigned kpass, unsigned kstart, unsigned kend,
    const float* w1, const float* w2, int rnext)
{
    constexpr int TW = NQ * 4;     // tokens this pass
    constexpr int DS = 4 / NQ;     // layer1 d-row sub-groups
    constexpr int R1 = 16 / DS;    // d-rows per thread per chunk
    constexpr int ES = 8 / NQ;     // layer2 e-row sub-groups
    constexpr int R2 = 32 / ES;    // e-rows per thread per chunk

    // ---- x tile (transposed [d][t], stride XSTR) into scratch ----
    for (int i = tid; i < TW * DMODEL; i += 256) {
        int t = i >> 7, d = i & (DMODEL - 1);
        scratch[d * XSTR + t] = (t < T) ? x[(size_t)toks[t] * DMODEL + d] : 0.0f;
    }
    __syncthreads();

    // ================= layer 1: chunks 0..7 (each [16 d][256 e]) =================
    const int e0   = (tid & 63) * 4;
    const int g1   = tid >> 6;              // 0..3
    const int tq1  = g1 % NQ;
    const int dsub = g1 / NQ;               // 0..DS-1
    const int t1   = tq1 * 4;
    const int row0 = dsub * R1;

    float acc[16];
    if (dsub == 0) {
        const float4 b = *(const float4*)&b1r[e0];
#pragma unroll
        for (int k = 0; k < 4; k++) {
            acc[0 + k] = b.x; acc[4 + k] = b.y; acc[8 + k] = b.z; acc[12 + k] = b.w;
        }
    } else {
#pragma unroll
        for (int i = 0; i < 16; i++) acc[i] = 0.0f;
    }

    for (int c = 0; c < 8; c++) {
        const unsigned K = kpass + c;
        mbar_wait(mb + (K & 3) * 8, (K >> 2) & 1);
        const float* Wc = wbuf + (K & 3) * CHUNKF;           // [16][256]
#pragma unroll
        for (int dd = 0; dd < R1; dd++) {
            const float4 w4 = *(const float4*)&Wc[(row0 + dd) * EDIM + e0];
            const float4 x4 = *(const float4*)&scratch[(c * 16 + row0 + dd) * XSTR + t1];
            const float wj[4] = {w4.x, w4.y, w4.z, w4.w};
            const float xk[4] = {x4.x, x4.y, x4.z, x4.w};
#pragma unroll
            for (int j = 0; j < 4; j++)
#pragma unroll
                for (int k = 0; k < 4; k++)
                    acc[j * 4 + k] += wj[j] * xk[k];
        }
        __syncthreads();   // slot reads done; (x tile dead after c==7)
        if (tid == 0) refill(sb, mb, K, kstart, kend, W1r, W2r, w1, w2, rnext);
    }

    // ---- reduce layer1 partials across dsub (single round; x tile dead) ----
    if (DS > 1) {
        if (dsub > 0) {
            float* reg = scratch + (dsub - 1) * (EDIM * TW);  // <= 3*1024 floats
#pragma unroll
            for (int j = 0; j < 4; j++) {
                float4 pv; pv.x = acc[j*4+0]; pv.y = acc[j*4+1]; pv.z = acc[j*4+2]; pv.w = acc[j*4+3];
                *(float4*)&reg[(e0 + j) * TW + t1] = pv;
            }
        }
        __syncthreads();
        if (dsub == 0) {
#pragma unroll
            for (int s = 0; s < DS - 1; s++) {
                const float* reg = scratch + s * (EDIM * TW);
#pragma unroll
                for (int j = 0; j < 4; j++) {
                    const float4 pv = *(const float4*)&reg[(e0 + j) * TW + t1];
                    acc[j*4+0] += pv.x; acc[j*4+1] += pv.y; acc[j*4+2] += pv.z; acc[j*4+3] += pv.w;
                }
            }
        }
    }

    // ---- gelu + hs store ----
    if (dsub == 0) {
#pragma unroll
        for (int j = 0; j < 4; j++) {
            float4 hv;
            hv.x = gelu_exact(acc[j*4+0]);
            hv.y = gelu_exact(acc[j*4+1]);
            hv.z = gelu_exact(acc[j*4+2]);
            hv.w = gelu_exact(acc[j*4+3]);
            *(float4*)&hs[(e0 + j) * HSTR + t1] = hv;
        }
    }
    __syncthreads();   // hs visible; scratch free for layer2 partials

    // ================= layer 2: chunks 8..15 (each [32 e][128 d]) =================
    const int d0   = (tid & 31) * 4;
    const int g2   = tid >> 5;              // 0..7
    const int tq2  = g2 % NQ;
    const int esub = g2 / NQ;               // 0..ES-1
    const int t2   = tq2 * 4;
    const int er0  = esub * R2;

    float a2[16];
#pragma unroll
    for (int i = 0; i < 16; i++) a2[i] = 0.0f;

    for (int c = 8; c < 16; c++) {
        const unsigned K = kpass + c;
        mbar_wait(mb + (K & 3) * 8, (K >> 2) & 1);
        const float* Wc = wbuf + (K & 3) * CHUNKF;           // [32][128]
        const int ebase = (c - 8) * 32;
#pragma unroll
        for (int ee = 0; ee < R2; ee++) {
            const float4 w4 = *(const float4*)&Wc[(er0 + ee) * DMODEL + d0];
            const float4 h4 = *(const float4*)&hs[(ebase + er0 + ee) * HSTR + t2];
            const float wj[4] = {w4.x, w4.y, w4.z, w4.w};
            const float hk[4] = {h4.x, h4.y, h4.z, h4.w};
#pragma unroll
            for (int j = 0; j < 4; j++)
#pragma unroll
                for (int k = 0; k < 4; k++)
                    a2[j * 4 + k] += wj[j] * hk[k];
        }
        __syncthreads();
        if (tid == 0) refill(sb, mb, K, kstart, kend, W1r, W2r, w1, w2, rnext);
    }

    // ---- reduce layer2 partials across esub (single round), bias, store ----
    if (esub > 0) {
        float* reg = scratch + (esub - 1) * (DMODEL * TW);   // <= 7*512 floats
#pragma unroll
        for (int j = 0; j < 4; j++) {
            float4 pv; pv.x = a2[j*4+0]; pv.y = a2[j*4+1]; pv.z = a2[j*4+2]; pv.w = a2[j*4+3];
            *(float4*)&reg[(d0 + j) * TW + t2] = pv;
        }
    }
    __syncthreads();
    if (esub == 0) {
#pragma unroll
        for (int s = 0; s < ES - 1; s++) {
            const float* reg = scratch + s * (DMODEL * TW);
#pragma unroll
            for (int j = 0; j < 4; j++) {
                const float4 pv = *(const float4*)&reg[(d0 + j) * TW + t2];
                a2[j*4+0] += pv.x; a2[j*4+1] += pv.y; a2[j*4+2] += pv.z; a2[j*4+3] += pv.w;
            }
        }
        const float4 b = *(const float4*)&b2r[d0];
#pragma unroll
        for (int k = 0; k < 4; k++) {
            const int t = t2 + k;
            if (t < T) {
                float4 o;
                o.x = a2[0 + k]  + b.x;
                o.y = a2[4 + k]  + b.y;
                o.z = a2[8 + k]  + b.z;
                o.w = a2[12 + k] + b.w;
                *(float4*)&out[(size_t)toks[t] * DMODEL + d0] = o;
            }
        }
    }
    __syncthreads();   // scratch/toks reuse safety
}

// Persistent CTAs, 256 threads, 2/SM. tid0 produces (TMA ring depth 4);
// all 8 warps consume every chunk.
__global__ __launch_bounds__(256, 2) void ffn_kernel(
    const float* __restrict__ x,
    const void*  __restrict__ rules,
    const float* __restrict__ w1,
    const float* __restrict__ b1,
    const float* __restrict__ w2,
    const float* __restrict__ b2,
    float* __restrict__ out,
    int n)
{
    extern __shared__ __align__(128) char smem[];
    float* wbuf    = (float*)(smem + WOFF);
    float* hs      = (float*)(smem + HOFF);
    float* scratch = (float*)(smem + SOFF);
    int*   toks    = (int*)(smem + TOKOFF);
    const uint32_t sb = smem_u32(smem);
    const uint32_t mb = sb + MBOFF;

    __shared__ int s_cnt;
    __shared__ int s_rnext;

    const int tid = threadIdx.x;
    if (tid < NSLOT) mbar_init(mb + tid * 8, 1);
    __syncthreads();

    int r = blockIdx.x;
    unsigned kg = 0;

    if (tid == 0) {    // prime the ring for the first rule
        const float* W1r = w1 + (size_t)r * 32768;
        const float* W2r = w2 + (size_t)r * 32768;
        for (int i = 0; i < NSLOT; i++) issue_chunk(sb, mb, kg + i, chunk_src(W1r, W2r, i));
    }

    while (r < NRULES) {
        if (tid == 0) s_cnt = 0;
        __syncthreads();

        // ---- gather this rule's tokens (vectorized; order irrelevant) ----
        if (g_is64 == 0) {
            const longlong2* rl = (const longlong2*)rules;
            for (int i = tid; i < n / 2; i += 256) {
                longlong2 v = rl[i];
                if ((int)v.x == r) { int p = atomicAdd(&s_cnt, 1); if (p < CAP) toks[p] = 2 * i; }
                if ((int)v.y == r) { int p = atomicAdd(&s_cnt, 1); if (p < CAP) toks[p] = 2 * i + 1; }
            }
        } else {
            const int4* rl = (const int4*)rules;
            for (int i = tid; i < n / 4; i += 256) {
                int4 v = rl[i];
                if (v.x == r) { int p = atomicAdd(&s_cnt, 1); if (p < CAP) toks[p] = 4 * i; }
                if (v.y == r) { int p = atomicAdd(&s_cnt, 1); if (p < CAP) toks[p] = 4 * i + 1; }
                if (v.z == r) { int p = atomicAdd(&s_cnt, 1); if (p < CAP) toks[p] = 4 * i + 2; }
                if (v.w == r) { int p = atomicAdd(&s_cnt, 1); if (p < CAP) toks[p] = 4 * i + 3; }
            }
        }
        if (tid == 0) s_rnext = (int)atomicAdd(&g_next, 1u);   // steal next rule
        __syncthreads();

        const int count = min(s_cnt, CAP);
        const int npass = (count > 0) ? (count + TMAX - 1) / TMAX : 1;  // stream ring even if empty
        const unsigned totalK = npass * 16;
        const int rnext = s_rnext;

        const float* W1r = w1 + (size_t)r * 32768;
        const float* W2r = w2 + (size_t)r * 32768;
        const float* b1r = b1 + (size_t)r * EDIM;
        const float* b2r = b2 + (size_t)r * DMODEL;

        for (int pass = 0; pass < npass; pass++) {
            const int base = pass * TMAX;
            int T = count - base; if (T > TMAX) T = TMAX; if (T < 0) T = 0;
            int NQ = (T + 3) >> 2; if (NQ < 1) NQ = 1; if (NQ == 3) NQ = 4;
            const unsigned kpass = kg + pass * 16;
            const unsigned kend  = kg + totalK;

            switch (NQ) {
                case 1: run_pass<1>(x, W1r, W2r, b1r, b2r, out, wbuf, hs, scratch,
                                    toks + base, sb, mb, T, tid, kpass, kg, kend,
                                    w1, w2, rnext); break;
                case 2: run_pass<2>(x, W1r, W2r, b1r, b2r, out, wbuf, hs, scratch,
                                    toks + base, sb, mb, T, tid, kpass, kg, kend,
                                    w1, w2, rnext); break;
                default: run_pass<4>(x, W1r, W2r, b1r, b2r, out, wbuf, hs, scratch,
                                    toks + base, sb, mb, T, tid, kpass, kg, kend,
                                    w1, w2, rnext); break;
            }
        }

        kg += totalK;
        r = rnext;
    }
}

extern "C" void kernel_launch(void* const* d_in, const int* in_sizes, int n_in,
                              void* d_out, int out_size)
{
    const float* x     = (const float*)d_in[0];
    const void*  rules = d_in[1];
    const float* w1    = (const float*)d_in[2];
    const float* b1    = (const float*)d_in[3];
    const float* w2    = (const float*)d_in[4];
    const float* b2    = (const float*)d_in[5];
    float*       out   = (float*)d_out;

    const int n = in_sizes[1];

    cudaFuncSetAttribute(ffn_kernel, cudaFuncAttributeMaxDynamicSharedMemorySize, SMEMSZ);

    detect_kernel<<<1, 256>>>((const unsigned int*)rules);   // also resets g_next
    ffn_kernel<<<GRID, 256, SMEMSZ>>>(x, rules, w1, b1, w2, b2, out, n);
}